// round 14
// baseline (speedup 1.0000x reference)
#include <cuda_runtime.h>

// Problem constants
#define Bn 2
#define Cn 32
#define INV8 0.3535533905932738f   // 1/(2*sqrt(2))
#define NBN 221184                 // 2 * 48^3

// Scratch (static device globals; no allocations allowed)
__device__ float g_part[64][18][8];         // parity partials [bc][slab][cls*2+eo]
__device__ float g_W2[Bn][Cn][8][Cn];       // [b][c][corner][o] folded weights
__device__ float g_sum[Cn];
__device__ float g_sq[Cn];

// ---------------------------------------------------------------------------
// Parity-class sums, pure streaming. Thread's float4 offset o0 in [0,4608);
// iteration stride 4608 float4 = 2 D-slices, so the (d,h) parity class of a
// thread is FIXED -> scalar register accumulators, fully contiguous warp loads.
__global__ void __launch_bounds__(256) k_parity(const float* __restrict__ x) {
    int bc = blockIdx.y;                 // 0..63
    int slab = blockIdx.x;               // 0..17
    int tid = threadIdx.x;
    int o0 = slab * 256 + tid;           // 0..4607
    int cls = ((o0 / 2304) & 1) * 2 + ((o0 / 24) & 1);   // dpar*2 + hpar

    const float4* q = (const float4*)x + (size_t)bc * 221184 + o0;
    float ae = 0.f, ao = 0.f;
#pragma unroll 8
    for (int it = 0; it < 48; it++) {
        float4 v = q[(size_t)it * 4608];
        ae += v.x + v.z;                 // even-w
        ao += v.y + v.w;                 // odd-w
    }

    __shared__ float acc[8];
    if (tid < 8) acc[tid] = 0.f;
    __syncthreads();
    atomicAdd(&acc[cls * 2 + 0], ae);
    atomicAdd(&acc[cls * 2 + 1], ao);
    __syncthreads();
    if (tid < 8) g_part[bc][slab][tid] = acc[tid];
}

// ---------------------------------------------------------------------------
// Slab reduce -> band means -> attention MLPs -> sigmoid scales -> folded W2.
// Also zeroes g_sum/g_sq for the conv's fused BN statistics.
// k = dpar*4 + hpar*2 + wpar matches band bit order; band 0 = aaa(low),
// bands 1..7 -> [aad,ada,add,daa,dad,dda,ddd] (z channel = 32 + c*7 + band-1).
__global__ void k_attn(const float* __restrict__ w1_low, const float* __restrict__ w2_low,
                       const float* __restrict__ w1_high, const float* __restrict__ w2_high,
                       const float* __restrict__ w_fuse) {
    __shared__ float S_sh[64][8];        // parity sums per (b,c)
    __shared__ float mean8[Bn][Cn][8];
    __shared__ float hl[Bn][2];
    __shared__ float hh[Bn][14];
    __shared__ float s_all[Bn][256];
    int tid = threadIdx.x;

    if (tid < 32) { g_sum[tid] = 0.f; g_sq[tid] = 0.f; }

    // reduce 18 slabs: 512 (bc, parity-class) entries
    for (int t = tid; t < 512; t += 256) {
        int bc = t >> 3, k = t & 7;
        float s = 0.f;
#pragma unroll
        for (int sl = 0; sl < 18; sl++) s += g_part[bc][sl][k];
        S_sh[bc][k] = s;
    }
    __syncthreads();

    if (tid < Bn * Cn) {
        int b = tid >> 5, c = tid & 31;
        float S[8];
#pragma unroll
        for (int p = 0; p < 8; p++) S[p] = S_sh[tid][p];
#pragma unroll
        for (int band = 0; band < 8; band++) {
            float m = 0.f;
#pragma unroll
            for (int p = 0; p < 8; p++)
                m += (__popc(band & p) & 1) ? -S[p] : S[p];
            mean8[b][c][band] = m * (INV8 / 110592.f);
        }
    }
    __syncthreads();

    if (tid < 4) {                       // low hidden: (B,2)
        int b = tid >> 1, r = tid & 1;
        float h = 0.f;
        for (int c = 0; c < 32; c++) h += mean8[b][c][0] * w1_low[r * 32 + c];
        hl[b][r] = fmaxf(h, 0.f);
    } else if (tid < 32) {               // high hidden: (B,14)
        int idx = tid - 4;
        int b = idx / 14, r = idx % 14;
        float h = 0.f;
        for (int j = 0; j < 224; j++)
            h += mean8[b][j / 7][1 + j % 7] * w1_high[r * 224 + j];
        hh[b][r] = fmaxf(h, 0.f);
    }
    __syncthreads();

    for (int t = tid; t < 512; t += 256) {   // sigmoid scales
        int b = t >> 8, ch = t & 255;
        float pre = 0.f;
        if (ch < 32) {
            for (int r = 0; r < 2; r++) pre += hl[b][r] * w2_low[ch * 2 + r];
        } else {
            int j = ch - 32;
            for (int r = 0; r < 14; r++) pre += hh[b][r] * w2_high[j * 14 + r];
        }
        s_all[b][ch] = 1.f / (1.f + expf(-pre));
    }
    __syncthreads();

    // W2[b][c][corner][o] = INV8 * sum_band sign(band,corner)*w_fuse[o,ch]*s[b,ch]
    for (int t = tid; t < 16384; t += 256) {
        int b = t >> 13;
        int c = (t >> 8) & 31;
        int corner = (t >> 5) & 7;
        int o = t & 31;
        float val = w_fuse[o * 256 + c] * s_all[b][c];   // band 0 (aaa)
#pragma unroll
        for (int band = 1; band < 8; band++) {
            int ch = 32 + c * 7 + band - 1;
            float term = w_fuse[o * 256 + ch] * s_all[b][ch];
            val += (__popc(band & corner) & 1) ? -term : term;
        }
        g_W2[b][c][corner][o] = val * INV8;
    }
}

// ---------------------------------------------------------------------------
// Packed fp32x2 helpers (Blackwell FFMA2 — only reachable via PTX)
__device__ __forceinline__ unsigned long long fma2(unsigned long long a,
                                                   unsigned long long b,
                                                   unsigned long long c) {
    unsigned long long d;
    asm("fma.rn.f32x2 %0, %1, %2, %3;" : "=l"(d) : "l"(a), "l"(b), "l"(c));
    return d;
}
__device__ __forceinline__ unsigned long long pack2(float lo, float hi) {
    unsigned long long r;
    asm("mov.b64 %0, {%1, %2};" : "=l"(r) : "f"(lo), "f"(hi));
    return r;
}
__device__ __forceinline__ void unpack2(unsigned long long v, float& lo, float& hi) {
    asm("mov.b64 {%0, %1}, %2;" : "=f"(lo), "=f"(hi) : "l"(v));
}

// cp.async helpers (Ampere+ LDGSTS)
__device__ __forceinline__ void cpa16(unsigned int dst, const float4* src) {
    asm volatile("cp.async.cg.shared.global [%0], [%1], 16;" :: "r"(dst), "l"(src));
}
#define CPA_COMMIT() asm volatile("cp.async.commit_group;")
#define CPA_WAIT2()  asm volatile("cp.async.wait_group 2;")

// ---------------------------------------------------------------------------
// Fused stride-2 2x2x2 conv + bias + BN-stat accumulation.
// x is staged through a 3-stage cp.async smem ring: each thread copies its own
// 4 float4 rows for channel c+2 while computing channel c from smem — LDG
// latency never touches the critical path, and no __syncthreads is needed in
// the loop (threads read only their own slots).
// Dynamic smem layout (84096 B):
//   [0,49152)        float4 xs[3][1024]   (x ring: stage s, thread tid -> tid*4..+3)
//   [49152,81920)    ulonglong2 swv[2048] (weights [c][corner] -> 8 ulonglong2)
//   [81920,82048)    float sb[32]
//   [82048,83072)    float redS[8][32]
//   [83072,84096)    float redQ[8][32]
__global__ void __launch_bounds__(256, 2) k_conv(const float* __restrict__ x,
                                                 const float* __restrict__ b_fuse,
                                                 float* __restrict__ out) {
    extern __shared__ char smem[];
    float4* xs = (float4*)smem;
    ulonglong2* swv = (ulonglong2*)(smem + 49152);
    float* sb = (float*)(smem + 81920);
    float* redS = (float*)(smem + 82048);
    float* redQ = (float*)(smem + 83072);

    int tid = threadIdx.x;
    int b = blockIdx.y;
    {
        float* swf = (float*)swv;
        const float* wsrc = &g_W2[b][0][0][0];
        for (int t = tid; t < 8192; t += 256) swf[t] = wsrc[t];
        if (tid < 32) sb[tid] = b_fuse[tid];
    }
    __syncthreads();

    int P = blockIdx.x * 256 + tid;      // 0..55295 (point-pair index)
    int t24 = P % 24;                    // output-W pair (w = 2*t24, 2*t24+1)
    int h = (P / 24) % 48;
    int d = P / 1152;

    const float4* xb = (const float4*)x;
    size_t base = (((size_t)(b * 32) * 96 + 2 * d) * 96 + 2 * h) * 24 + t24;

    unsigned int xs_smem = (unsigned int)__cvta_generic_to_shared(xs) + tid * 64;

    unsigned long long accA[16], accB[16];
#pragma unroll
    for (int i = 0; i < 16; i++) { accA[i] = 0ull; accB[i] = 0ull; }

    // prologue: stage channels 0 and 1
#pragma unroll
    for (int s = 0; s < 2; s++) {
        const float4* ps = xb + base + (size_t)s * 221184;
        unsigned int dst = xs_smem + s * 16384;
        cpa16(dst + 0, ps + 0);
        cpa16(dst + 16, ps + 24);
        cpa16(dst + 32, ps + 2304);
        cpa16(dst + 48, ps + 2328);
        CPA_COMMIT();
    }

    int s = 0;                            // ring stage of channel c
#pragma unroll 1
    for (int c = 0; c < 32; c++) {
        if (c + 2 < 32) {                 // stage channel c+2 into ring slot (s+2)%3
            int sn = s + 2; if (sn >= 3) sn -= 3;
            const float4* ps = xb + base + (size_t)(c + 2) * 221184;
            unsigned int dst = xs_smem + sn * 16384;
            cpa16(dst + 0, ps + 0);
            cpa16(dst + 16, ps + 24);
            cpa16(dst + 32, ps + 2304);
            cpa16(dst + 48, ps + 2328);
        }
        CPA_COMMIT();                     // one group per iteration (maybe empty)
        CPA_WAIT2();                      // <=2 pending -> stage c complete

        const float4* xsl = xs + s * 1024 + tid * 4;
        float4 cur0 = xsl[0];             // (i=0,j=0)
        float4 cur1 = xsl[1];             // (i=0,j=1)
        float4 cur2 = xsl[2];             // (i=1,j=0)
        float4 cur3 = xsl[3];             // (i=1,j=1)

        float xA[8], xB[8];               // corner = i*4 + j*2 + k
        xA[0] = cur0.x; xB[0] = cur0.z;  xA[1] = cur0.y; xB[1] = cur0.w;
        xA[2] = cur1.x; xB[2] = cur1.z;  xA[3] = cur1.y; xB[3] = cur1.w;
        xA[4] = cur2.x; xB[4] = cur2.z;  xA[5] = cur2.y; xB[5] = cur2.w;
        xA[6] = cur3.x; xB[6] = cur3.z;  xA[7] = cur3.y; xB[7] = cur3.w;
#pragma unroll
        for (int corner = 0; corner < 8; corner++) {
            unsigned long long a2 = pack2(xA[corner], xA[corner]);
            unsigned long long b2 = pack2(xB[corner], xB[corner]);
            const ulonglong2* wq = swv + (c * 8 + corner) * 8;
#pragma unroll
            for (int q = 0; q < 8; q++) {
                ulonglong2 w = wq[q];     // LDS.128: w.x={o:4q,4q+1}, w.y={o:4q+2,4q+3}
                accA[2 * q]     = fma2(w.x, a2, accA[2 * q]);
                accB[2 * q]     = fma2(w.x, b2, accB[2 * q]);
                accA[2 * q + 1] = fma2(w.y, a2, accA[2 * q + 1]);
                accB[2 * q + 1] = fma2(w.y, b2, accB[2 * q + 1]);
            }
        }
        s = s + 1; if (s == 3) s = 0;
    }

    // epilogue: bias + coalesced float2 stores + fused BN statistics
    size_t obase2 = (size_t)(b * 32) * 55296 + (size_t)d * 1152 + (size_t)h * 24 + t24;
    float2* o2 = (float2*)out;
    int warp = tid >> 5, lane = tid & 31;
#pragma unroll
    for (int op = 0; op < 16; op++) {
        float a0, a1, b0, b1;
        unpack2(accA[op], a0, a1);
        unpack2(accB[op], b0, b1);
        float bias0 = sb[2 * op], bias1 = sb[2 * op + 1];
        float zA0 = a0 + bias0, zB0 = b0 + bias0;   // channel 2op, w / w+1
        float zA1 = a1 + bias1, zB1 = b1 + bias1;   // channel 2op+1
        float2 v0; v0.x = zA0; v0.y = zB0;
        float2 v1; v1.x = zA1; v1.y = zB1;
        o2[obase2 + (size_t)(2 * op) * 55296] = v0;
        o2[obase2 + (size_t)(2 * op + 1) * 55296] = v1;
        // BN stats on pre-ReLU z
        float s0 = zA0 + zB0, q0 = zA0 * zA0 + zB0 * zB0;
        float s1 = zA1 + zB1, q1 = zA1 * zA1 + zB1 * zB1;
#pragma unroll
        for (int sh = 16; sh > 0; sh >>= 1) {
            s0 += __shfl_xor_sync(0xffffffffu, s0, sh);
            q0 += __shfl_xor_sync(0xffffffffu, q0, sh);
            s1 += __shfl_xor_sync(0xffffffffu, s1, sh);
            q1 += __shfl_xor_sync(0xffffffffu, q1, sh);
        }
        if (lane == 0) {
            redS[warp * 32 + 2 * op] = s0; redQ[warp * 32 + 2 * op] = q0;
            redS[warp * 32 + 2 * op + 1] = s1; redQ[warp * 32 + 2 * op + 1] = q1;
        }
    }
    __syncthreads();
    if (tid < 64) {
        int o = tid & 31;
        if (tid < 32) {
            float S = 0.f;
#pragma unroll
            for (int w = 0; w < 8; w++) S += redS[w * 32 + o];
            atomicAdd(&g_sum[o], S);
        } else {
            float Q = 0.f;
#pragma unroll
            for (int w = 0; w < 8; w++) Q += redQ[w * 32 + o];
            atomicAdd(&g_sq[o], Q);
        }
    }
}

// ---------------------------------------------------------------------------
// In-place BatchNorm (batch stats) + affine + ReLU.
__global__ void k_final(float* __restrict__ z, const float* __restrict__ gamma,
                        const float* __restrict__ beta) {
    int idx = blockIdx.x * 256 + threadIdx.x;   // float4 index, total 1769472
    int o = (idx / 27648) & 31;                 // 27648 float4 per (b,o) plane
    float mu = g_sum[o] * (1.f / (float)NBN);
    float var = g_sq[o] * (1.f / (float)NBN) - mu * mu;
    float inv = rsqrtf(var + 1e-5f);
    float sc = gamma[o] * inv;
    float sh = beta[o] - mu * sc;
    float4* p = (float4*)z;
    float4 v = p[idx];
    v.x = fmaxf(v.x * sc + sh, 0.f);
    v.y = fmaxf(v.y * sc + sh, 0.f);
    v.z = fmaxf(v.z * sc + sh, 0.f);
    v.w = fmaxf(v.w * sc + sh, 0.f);
    p[idx] = v;
}

// ---------------------------------------------------------------------------
#define CONV_SMEM 84096

extern "C" void kernel_launch(void* const* d_in, const int* in_sizes, int n_in,
                              void* d_out, int out_size) {
    const float* x       = (const float*)d_in[0];
    const float* w1_low  = (const float*)d_in[1];
    const float* w2_low  = (const float*)d_in[2];
    const float* w1_high = (const float*)d_in[3];
    const float* w2_high = (const float*)d_in[4];
    const float* w_fuse  = (const float*)d_in[5];
    const float* b_fuse  = (const float*)d_in[6];
    const float* gamma   = (const float*)d_in[7];
    const float* beta    = (const float*)d_in[8];
    float* out = (float*)d_out;

    cudaFuncSetAttribute(k_conv, cudaFuncAttributeMaxDynamicSharedMemorySize, CONV_SMEM);

    k_parity<<<dim3(18, 64), 256>>>(x);
    k_attn<<<1, 256>>>(w1_low, w2_low, w1_high, w2_high, w_fuse);
    k_conv<<<dim3(216, 2), 256, CONV_SMEM>>>(x, b_fuse, out);
    k_final<<<6912, 256>>>(out, gamma, beta);
}

// round 15
// speedup vs baseline: 1.1191x; 1.1191x over previous
#include <cuda_runtime.h>

// Problem constants
#define Bn 2
#define Cn 32
#define INV8 0.3535533905932738f   // 1/(2*sqrt(2))
#define NBN 221184                 // 2 * 48^3

// Scratch (static device globals; no allocations allowed)
__device__ float g_part[64][18][8];         // parity partials [bc][slab][cls*2+eo]
__device__ float g_W2[Bn][Cn][8][Cn];       // [b][c][corner][o] folded weights
__device__ float g_sum[Cn];
__device__ float g_sq[Cn];

// ---------------------------------------------------------------------------
// Parity-class sums, pure streaming. Thread's float4 offset o0 in [0,4608);
// iteration stride 4608 float4 = 2 D-slices, so the (d,h) parity class of a
// thread is FIXED -> scalar register accumulators, fully contiguous warp loads.
__global__ void __launch_bounds__(256) k_parity(const float* __restrict__ x) {
    int bc = blockIdx.y;                 // 0..63
    int slab = blockIdx.x;               // 0..17
    int tid = threadIdx.x;
    int o0 = slab * 256 + tid;           // 0..4607
    int cls = ((o0 / 2304) & 1) * 2 + ((o0 / 24) & 1);   // dpar*2 + hpar

    const float4* q = (const float4*)x + (size_t)bc * 221184 + o0;
    float ae = 0.f, ao = 0.f;
#pragma unroll 8
    for (int it = 0; it < 48; it++) {
        float4 v = q[(size_t)it * 4608];
        ae += v.x + v.z;                 // even-w
        ao += v.y + v.w;                 // odd-w
    }

    __shared__ float acc[8];
    if (tid < 8) acc[tid] = 0.f;
    __syncthreads();
    atomicAdd(&acc[cls * 2 + 0], ae);
    atomicAdd(&acc[cls * 2 + 1], ao);
    __syncthreads();
    if (tid < 8) g_part[bc][slab][tid] = acc[tid];
}

// ---------------------------------------------------------------------------
// Slab reduce -> band means -> attention MLPs -> sigmoid scales -> folded W2.
// Also zeroes g_sum/g_sq for the conv's fused BN statistics.
__global__ void k_attn(const float* __restrict__ w1_low, const float* __restrict__ w2_low,
                       const float* __restrict__ w1_high, const float* __restrict__ w2_high,
                       const float* __restrict__ w_fuse) {
    __shared__ float S_sh[64][8];        // parity sums per (b,c)
    __shared__ float mean8[Bn][Cn][8];
    __shared__ float hl[Bn][2];
    __shared__ float hh[Bn][14];
    __shared__ float s_all[Bn][256];
    int tid = threadIdx.x;

    if (tid < 32) { g_sum[tid] = 0.f; g_sq[tid] = 0.f; }

    // reduce 18 slabs: 512 (bc, parity-class) entries
    for (int t = tid; t < 512; t += 256) {
        int bc = t >> 3, k = t & 7;
        float s = 0.f;
#pragma unroll
        for (int sl = 0; sl < 18; sl++) s += g_part[bc][sl][k];
        S_sh[bc][k] = s;
    }
    __syncthreads();

    if (tid < Bn * Cn) {
        int b = tid >> 5, c = tid & 31;
        float S[8];
#pragma unroll
        for (int p = 0; p < 8; p++) S[p] = S_sh[tid][p];
#pragma unroll
        for (int band = 0; band < 8; band++) {
            float m = 0.f;
#pragma unroll
            for (int p = 0; p < 8; p++)
                m += (__popc(band & p) & 1) ? -S[p] : S[p];
            mean8[b][c][band] = m * (INV8 / 110592.f);
        }
    }
    __syncthreads();

    if (tid < 4) {                       // low hidden: (B,2)
        int b = tid >> 1, r = tid & 1;
        float h = 0.f;
        for (int c = 0; c < 32; c++) h += mean8[b][c][0] * w1_low[r * 32 + c];
        hl[b][r] = fmaxf(h, 0.f);
    } else if (tid < 32) {               // high hidden: (B,14)
        int idx = tid - 4;
        int b = idx / 14, r = idx % 14;
        float h = 0.f;
        for (int j = 0; j < 224; j++)
            h += mean8[b][j / 7][1 + j % 7] * w1_high[r * 224 + j];
        hh[b][r] = fmaxf(h, 0.f);
    }
    __syncthreads();

    for (int t = tid; t < 512; t += 256) {   // sigmoid scales
        int b = t >> 8, ch = t & 255;
        float pre = 0.f;
        if (ch < 32) {
            for (int r = 0; r < 2; r++) pre += hl[b][r] * w2_low[ch * 2 + r];
        } else {
            int j = ch - 32;
            for (int r = 0; r < 14; r++) pre += hh[b][r] * w2_high[j * 14 + r];
        }
        s_all[b][ch] = 1.f / (1.f + expf(-pre));
    }
    __syncthreads();

    // W2[b][c][corner][o] = INV8 * sum_band sign(band,corner)*w_fuse[o,ch]*s[b,ch]
    for (int t = tid; t < 16384; t += 256) {
        int b = t >> 13;
        int c = (t >> 8) & 31;
        int corner = (t >> 5) & 7;
        int o = t & 31;
        float val = w_fuse[o * 256 + c] * s_all[b][c];   // band 0 (aaa)
#pragma unroll
        for (int band = 1; band < 8; band++) {
            int ch = 32 + c * 7 + band - 1;
            float term = w_fuse[o * 256 + ch] * s_all[b][ch];
            val += (__popc(band & corner) & 1) ? -term : term;
        }
        g_W2[b][c][corner][o] = val * INV8;
    }
}

// ---------------------------------------------------------------------------
// Packed fp32x2 helpers (Blackwell FFMA2 — only reachable via PTX)
__device__ __forceinline__ unsigned long long fma2(unsigned long long a,
                                                   unsigned long long b,
                                                   unsigned long long c) {
    unsigned long long d;
    asm("fma.rn.f32x2 %0, %1, %2, %3;" : "=l"(d) : "l"(a), "l"(b), "l"(c));
    return d;
}
__device__ __forceinline__ unsigned long long pack2(float lo, float hi) {
    unsigned long long r;
    asm("mov.b64 %0, {%1, %2};" : "=l"(r) : "f"(lo), "f"(hi));
    return r;
}
__device__ __forceinline__ void unpack2(unsigned long long v, float& lo, float& hi) {
    asm("mov.b64 {%0, %1}, %2;" : "=f"(lo), "=f"(hi) : "l"(v));
}

// ---------------------------------------------------------------------------
// Fused stride-2 2x2x2 conv + bias + BN-stat accumulation.
// Register-prefetch software pipeline at DISTANCE 2: while computing channel c,
// the rows for c+1 sit in registers and the LDGs for c+2 are in flight —
// ~2 full corner-loops (~2700 issue cycles) between LDG issue and first use.
__global__ void __launch_bounds__(256, 2) k_conv(const float* __restrict__ x,
                                                 const float* __restrict__ b_fuse,
                                                 float* __restrict__ out) {
    __shared__ ulonglong2 swv[2048];     // 32 KB: [c][corner] -> 8 ulonglong2 each
    __shared__ float sb[Cn];
    __shared__ float redS[8][Cn];
    __shared__ float redQ[8][Cn];
    int tid = threadIdx.x;
    int b = blockIdx.y;
    {
        float* swf = (float*)swv;
        const float* wsrc = &g_W2[b][0][0][0];
        for (int t = tid; t < 8192; t += 256) swf[t] = wsrc[t];
        if (tid < 32) sb[tid] = b_fuse[tid];
    }
    __syncthreads();

    int P = blockIdx.x * 256 + tid;      // 0..55295 (point-pair index)
    int t24 = P % 24;                    // output-W pair (w = 2*t24, 2*t24+1)
    int h = (P / 24) % 48;
    int d = P / 1152;

    const float4* xb = (const float4*)x;
    size_t base = (((size_t)(b * 32) * 96 + 2 * d) * 96 + 2 * h) * 24 + t24;

    unsigned long long accA[16], accB[16];
#pragma unroll
    for (int i = 0; i < 16; i++) { accA[i] = 0ull; accB[i] = 0ull; }

    // prologue: rows for c = 0 (cur) and c = 1 (nx)
    float4 cur0, cur1, cur2, cur3;
    float4 nx0, nx1, nx2, nx3;
    {
        const float4* p = xb + base;
        cur0 = p[0]; cur1 = p[24]; cur2 = p[2304]; cur3 = p[2328];
        const float4* q = xb + base + 221184;
        nx0 = q[0]; nx1 = q[24]; nx2 = q[2304]; nx3 = q[2328];
    }

#pragma unroll 2
    for (int c = 0; c < 32; c++) {
        // issue LDGs for c+2 (wraps harmlessly at the tail; values unused)
        float4 nn0, nn1, nn2, nn3;
        {
            const float4* p = xb + base + (size_t)((c + 2) & 31) * 221184;
            nn0 = p[0]; nn1 = p[24]; nn2 = p[2304]; nn3 = p[2328];
        }

        float xA[8], xB[8];              // corner = i*4 + j*2 + k
        xA[0] = cur0.x; xB[0] = cur0.z;  xA[1] = cur0.y; xB[1] = cur0.w;
        xA[2] = cur1.x; xB[2] = cur1.z;  xA[3] = cur1.y; xB[3] = cur1.w;
        xA[4] = cur2.x; xB[4] = cur2.z;  xA[5] = cur2.y; xB[5] = cur2.w;
        xA[6] = cur3.x; xB[6] = cur3.z;  xA[7] = cur3.y; xB[7] = cur3.w;
#pragma unroll
        for (int corner = 0; corner < 8; corner++) {
            unsigned long long a2 = pack2(xA[corner], xA[corner]);
            unsigned long long b2 = pack2(xB[corner], xB[corner]);
            const ulonglong2* wq = swv + (c * 8 + corner) * 8;
#pragma unroll
            for (int q = 0; q < 8; q++) {
                ulonglong2 w = wq[q];    // LDS.128: w.x={o:4q,4q+1}, w.y={o:4q+2,4q+3}
                accA[2 * q]     = fma2(w.x, a2, accA[2 * q]);
                accB[2 * q]     = fma2(w.x, b2, accB[2 * q]);
                accA[2 * q + 1] = fma2(w.y, a2, accA[2 * q + 1]);
                accB[2 * q + 1] = fma2(w.y, b2, accB[2 * q + 1]);
            }
        }
        cur0 = nx0; cur1 = nx1; cur2 = nx2; cur3 = nx3;
        nx0 = nn0; nx1 = nn1; nx2 = nn2; nx3 = nn3;
    }

    // epilogue: bias + coalesced float2 stores + fused BN statistics
    size_t obase2 = (size_t)(b * 32) * 55296 + (size_t)d * 1152 + (size_t)h * 24 + t24;
    float2* o2 = (float2*)out;
    int warp = tid >> 5, lane = tid & 31;
#pragma unroll
    for (int op = 0; op < 16; op++) {
        float a0, a1, b0, b1;
        unpack2(accA[op], a0, a1);
        unpack2(accB[op], b0, b1);
        float bias0 = sb[2 * op], bias1 = sb[2 * op + 1];
        float zA0 = a0 + bias0, zB0 = b0 + bias0;   // channel 2op, w / w+1
        float zA1 = a1 + bias1, zB1 = b1 + bias1;   // channel 2op+1
        float2 v0; v0.x = zA0; v0.y = zB0;
        float2 v1; v1.x = zA1; v1.y = zB1;
        o2[obase2 + (size_t)(2 * op) * 55296] = v0;
        o2[obase2 + (size_t)(2 * op + 1) * 55296] = v1;
        // BN stats on pre-ReLU z
        float s0 = zA0 + zB0, q0 = zA0 * zA0 + zB0 * zB0;
        float s1 = zA1 + zB1, q1 = zA1 * zA1 + zB1 * zB1;
#pragma unroll
        for (int sh = 16; sh > 0; sh >>= 1) {
            s0 += __shfl_xor_sync(0xffffffffu, s0, sh);
            q0 += __shfl_xor_sync(0xffffffffu, q0, sh);
            s1 += __shfl_xor_sync(0xffffffffu, s1, sh);
            q1 += __shfl_xor_sync(0xffffffffu, q1, sh);
        }
        if (lane == 0) {
            redS[warp][2 * op] = s0; redQ[warp][2 * op] = q0;
            redS[warp][2 * op + 1] = s1; redQ[warp][2 * op + 1] = q1;
        }
    }
    __syncthreads();
    if (tid < 64) {
        int o = tid & 31;
        if (tid < 32) {
            float S = 0.f;
#pragma unroll
            for (int w = 0; w < 8; w++) S += redS[w][o];
            atomicAdd(&g_sum[o], S);
        } else {
            float Q = 0.f;
#pragma unroll
            for (int w = 0; w < 8; w++) Q += redQ[w][o];
            atomicAdd(&g_sq[o], Q);
        }
    }
}

// ---------------------------------------------------------------------------
// In-place BatchNorm (batch stats) + affine + ReLU.
__global__ void k_final(float* __restrict__ z, const float* __restrict__ gamma,
                        const float* __restrict__ beta) {
    int idx = blockIdx.x * 256 + threadIdx.x;   // float4 index, total 1769472
    int o = (idx / 27648) & 31;                 // 27648 float4 per (b,o) plane
    float mu = g_sum[o] * (1.f / (float)NBN);
    float var = g_sq[o] * (1.f / (float)NBN) - mu * mu;
    float inv = rsqrtf(var + 1e-5f);
    float sc = gamma[o] * inv;
    float sh = beta[o] - mu * sc;
    float4* p = (float4*)z;
    float4 v = p[idx];
    v.x = fmaxf(v.x * sc + sh, 0.f);
    v.y = fmaxf(v.y * sc + sh, 0.f);
    v.z = fmaxf(v.z * sc + sh, 0.f);
    v.w = fmaxf(v.w * sc + sh, 0.f);
    p[idx] = v;
}

// ---------------------------------------------------------------------------
extern "C" void kernel_launch(void* const* d_in, const int* in_sizes, int n_in,
                              void* d_out, int out_size) {
    const float* x       = (const float*)d_in[0];
    const float* w1_low  = (const float*)d_in[1];
    const float* w2_low  = (const float*)d_in[2];
    const float* w1_high = (const float*)d_in[3];
    const float* w2_high = (const float*)d_in[4];
    const float* w_fuse  = (const float*)d_in[5];
    const float* b_fuse  = (const float*)d_in[6];
    const float* gamma   = (const float*)d_in[7];
    const float* beta    = (const float*)d_in[8];
    float* out = (float*)d_out;

    k_parity<<<dim3(18, 64), 256>>>(x);
    k_attn<<<1, 256>>>(w1_low, w2_low, w1_high, w2_high, w_fuse);
    k_conv<<<dim3(216, 2), 256>>>(x, b_fuse, out);
    k_final<<<6912, 256>>>(out, gamma, beta);
}

// round 17
// speedup vs baseline: 1.1415x; 1.0201x over previous
#include <cuda_runtime.h>

// Problem constants
#define Bn 2
#define Cn 32
#define INV8 0.3535533905932738f   // 1/(2*sqrt(2))
#define NBN 221184                 // 2 * 48^3

// Scratch (static device globals; no allocations allowed)
__device__ float g_part[64][18][8];         // parity partials [bc][slab][cls*2+eo]
__device__ float g_W2[Bn][Cn][8][Cn];       // [b][c][corner][o] folded weights
__device__ float g_sum[Cn];
__device__ float g_sq[Cn];

// ---------------------------------------------------------------------------
// Parity-class sums, pure streaming. Thread's float4 offset o0 in [0,4608);
// iteration stride 4608 float4 = 2 D-slices, so the (d,h) parity class of a
// thread is FIXED -> scalar register accumulators, fully contiguous warp loads.
__global__ void __launch_bounds__(256) k_parity(const float* __restrict__ x) {
    int bc = blockIdx.y;                 // 0..63
    int slab = blockIdx.x;               // 0..17
    int tid = threadIdx.x;
    int o0 = slab * 256 + tid;           // 0..4607
    int cls = ((o0 / 2304) & 1) * 2 + ((o0 / 24) & 1);   // dpar*2 + hpar

    const float4* q = (const float4*)x + (size_t)bc * 221184 + o0;
    float ae = 0.f, ao = 0.f;
#pragma unroll 8
    for (int it = 0; it < 48; it++) {
        float4 v = q[(size_t)it * 4608];
        ae += v.x + v.z;                 // even-w
        ao += v.y + v.w;                 // odd-w
    }

    __shared__ float acc[8];
    if (tid < 8) acc[tid] = 0.f;
    __syncthreads();
    atomicAdd(&acc[cls * 2 + 0], ae);
    atomicAdd(&acc[cls * 2 + 1], ao);
    __syncthreads();
    if (tid < 8) g_part[bc][slab][tid] = acc[tid];
}

// ---------------------------------------------------------------------------
// Slab reduce -> band means -> attention MLPs -> sigmoid scales -> folded W2.
// Also zeroes g_sum/g_sq for the conv's fused BN statistics.
__global__ void k_attn(const float* __restrict__ w1_low, const float* __restrict__ w2_low,
                       const float* __restrict__ w1_high, const float* __restrict__ w2_high,
                       const float* __restrict__ w_fuse) {
    __shared__ float S_sh[64][8];        // parity sums per (b,c)
    __shared__ float mean8[Bn][Cn][8];
    __shared__ float hl[Bn][2];
    __shared__ float hh[Bn][14];
    __shared__ float s_all[Bn][256];
    int tid = threadIdx.x;

    if (tid < 32) { g_sum[tid] = 0.f; g_sq[tid] = 0.f; }

    // reduce 18 slabs: 512 (bc, parity-class) entries
    for (int t = tid; t < 512; t += 256) {
        int bc = t >> 3, k = t & 7;
        float s = 0.f;
#pragma unroll
        for (int sl = 0; sl < 18; sl++) s += g_part[bc][sl][k];
        S_sh[bc][k] = s;
    }
    __syncthreads();

    if (tid < Bn * Cn) {
        int b = tid >> 5, c = tid & 31;
        float S[8];
#pragma unroll
        for (int p = 0; p < 8; p++) S[p] = S_sh[tid][p];
#pragma unroll
        for (int band = 0; band < 8; band++) {
            float m = 0.f;
#pragma unroll
            for (int p = 0; p < 8; p++)
                m += (__popc(band & p) & 1) ? -S[p] : S[p];
            mean8[b][c][band] = m * (INV8 / 110592.f);
        }
    }
    __syncthreads();

    if (tid < 4) {                       // low hidden: (B,2)
        int b = tid >> 1, r = tid & 1;
        float h = 0.f;
        for (int c = 0; c < 32; c++) h += mean8[b][c][0] * w1_low[r * 32 + c];
        hl[b][r] = fmaxf(h, 0.f);
    } else if (tid < 32) {               // high hidden: (B,14)
        int idx = tid - 4;
        int b = idx / 14, r = idx % 14;
        float h = 0.f;
        for (int j = 0; j < 224; j++)
            h += mean8[b][j / 7][1 + j % 7] * w1_high[r * 224 + j];
        hh[b][r] = fmaxf(h, 0.f);
    }
    __syncthreads();

    for (int t = tid; t < 512; t += 256) {   // sigmoid scales
        int b = t >> 8, ch = t & 255;
        float pre = 0.f;
        if (ch < 32) {
            for (int r = 0; r < 2; r++) pre += hl[b][r] * w2_low[ch * 2 + r];
        } else {
            int j = ch - 32;
            for (int r = 0; r < 14; r++) pre += hh[b][r] * w2_high[j * 14 + r];
        }
        s_all[b][ch] = 1.f / (1.f + expf(-pre));
    }
    __syncthreads();

    // W2[b][c][corner][o] = INV8 * sum_band sign(band,corner)*w_fuse[o,ch]*s[b,ch]
    for (int t = tid; t < 16384; t += 256) {
        int b = t >> 13;
        int c = (t >> 8) & 31;
        int corner = (t >> 5) & 7;
        int o = t & 31;
        float val = w_fuse[o * 256 + c] * s_all[b][c];   // band 0 (aaa)
#pragma unroll
        for (int band = 1; band < 8; band++) {
            int ch = 32 + c * 7 + band - 1;
            float term = w_fuse[o * 256 + ch] * s_all[b][ch];
            val += (__popc(band & corner) & 1) ? -term : term;
        }
        g_W2[b][c][corner][o] = val * INV8;
    }
}

// ---------------------------------------------------------------------------
// Packed fp32x2 helpers (Blackwell FFMA2 — only reachable via PTX)
__device__ __forceinline__ unsigned long long fma2(unsigned long long a,
                                                   unsigned long long b,
                                                   unsigned long long c) {
    unsigned long long d;
    asm("fma.rn.f32x2 %0, %1, %2, %3;" : "=l"(d) : "l"(a), "l"(b), "l"(c));
    return d;
}
__device__ __forceinline__ unsigned long long pack2(float lo, float hi) {
    unsigned long long r;
    asm("mov.b64 %0, {%1, %2};" : "=l"(r) : "f"(lo), "f"(hi));
    return r;
}
__device__ __forceinline__ void unpack2(unsigned long long v, float& lo, float& hi) {
    asm("mov.b64 {%0, %1}, %2;" : "=f"(lo), "=f"(hi) : "l"(v));
}

// ---------------------------------------------------------------------------
// Fused stride-2 2x2x2 conv + bias + BN-stat accumulation.
// Register-prefetch software pipeline at distance 1 (the R11 configuration:
// 102 regs, no spills). The 4 x-row float4s for iteration c+1 are issued
// before the corner/FMA loop of iteration c.
__global__ void __launch_bounds__(256, 2) k_conv(const float* __restrict__ x,
                                                 const float* __restrict__ b_fuse,
                                                 float* __restrict__ out) {
    __shared__ ulonglong2 swv[2048];     // 32 KB: [c][corner] -> 8 ulonglong2 each
    __shared__ float sb[Cn];
    __shared__ float redS[8][Cn];
    __shared__ float redQ[8][Cn];
    int tid = threadIdx.x;
    int b = blockIdx.y;
    {
        float* swf = (float*)swv;
        const float* wsrc = &g_W2[b][0][0][0];
        for (int t = tid; t < 8192; t += 256) swf[t] = wsrc[t];
        if (tid < 32) sb[tid] = b_fuse[tid];
    }
    __syncthreads();

    int P = blockIdx.x * 256 + tid;      // 0..55295 (point-pair index)
    int t24 = P % 24;                    // output-W pair (w = 2*t24, 2*t24+1)
    int h = (P / 24) % 48;
    int d = P / 1152;

    const float4* xb = (const float4*)x;
    size_t base = (((size_t)(b * 32) * 96 + 2 * d) * 96 + 2 * h) * 24 + t24;

    unsigned long long accA[16], accB[16];
#pragma unroll
    for (int i = 0; i < 16; i++) { accA[i] = 0ull; accB[i] = 0ull; }

    // prologue: load rows for c = 0
    float4 cur0, cur1, cur2, cur3;
    {
        const float4* p = xb + base;
        cur0 = p[0]; cur1 = p[24]; cur2 = p[2304]; cur3 = p[2328];
    }

#pragma unroll 2
    for (int c = 0; c < 32; c++) {
        // prefetch next iteration's rows (wraps to c=0 at the end; unused)
        float4 n0, n1, n2, n3;
        {
            const float4* p = xb + base + (size_t)((c + 1) & 31) * 221184;
            n0 = p[0]; n1 = p[24]; n2 = p[2304]; n3 = p[2328];
        }

        float xA[8], xB[8];              // corner = i*4 + j*2 + k
        xA[0] = cur0.x; xB[0] = cur0.z;  xA[1] = cur0.y; xB[1] = cur0.w;
        xA[2] = cur1.x; xB[2] = cur1.z;  xA[3] = cur1.y; xB[3] = cur1.w;
        xA[4] = cur2.x; xB[4] = cur2.z;  xA[5] = cur2.y; xB[5] = cur2.w;
        xA[6] = cur3.x; xB[6] = cur3.z;  xA[7] = cur3.y; xB[7] = cur3.w;
#pragma unroll
        for (int corner = 0; corner < 8; corner++) {
            unsigned long long a2 = pack2(xA[corner], xA[corner]);
            unsigned long long b2 = pack2(xB[corner], xB[corner]);
            const ulonglong2* wq = swv + (c * 8 + corner) * 8;
#pragma unroll
            for (int q = 0; q < 8; q++) {
                ulonglong2 w = wq[q];    // LDS.128: w.x={o:4q,4q+1}, w.y={o:4q+2,4q+3}
                accA[2 * q]     = fma2(w.x, a2, accA[2 * q]);
                accB[2 * q]     = fma2(w.x, b2, accB[2 * q]);
                accA[2 * q + 1] = fma2(w.y, a2, accA[2 * q + 1]);
                accB[2 * q + 1] = fma2(w.y, b2, accB[2 * q + 1]);
            }
        }
        cur0 = n0; cur1 = n1; cur2 = n2; cur3 = n3;
    }

    // epilogue: bias + coalesced float2 stores + fused BN statistics
    size_t obase2 = (size_t)(b * 32) * 55296 + (size_t)d * 1152 + (size_t)h * 24 + t24;
    float2* o2 = (float2*)out;
    int warp = tid >> 5, lane = tid & 31;
#pragma unroll
    for (int op = 0; op < 16; op++) {
        float a0, a1, b0, b1;
        unpack2(accA[op], a0, a1);
        unpack2(accB[op], b0, b1);
        float bias0 = sb[2 * op], bias1 = sb[2 * op + 1];
        float zA0 = a0 + bias0, zB0 = b0 + bias0;   // channel 2op, w / w+1
        float zA1 = a1 + bias1, zB1 = b1 + bias1;   // channel 2op+1
        float2 v0; v0.x = zA0; v0.y = zB0;
        float2 v1; v1.x = zA1; v1.y = zB1;
        o2[obase2 + (size_t)(2 * op) * 55296] = v0;
        o2[obase2 + (size_t)(2 * op + 1) * 55296] = v1;
        // BN stats on pre-ReLU z
        float s0 = zA0 + zB0, q0 = zA0 * zA0 + zB0 * zB0;
        float s1 = zA1 + zB1, q1 = zA1 * zA1 + zB1 * zB1;
#pragma unroll
        for (int sh = 16; sh > 0; sh >>= 1) {
            s0 += __shfl_xor_sync(0xffffffffu, s0, sh);
            q0 += __shfl_xor_sync(0xffffffffu, q0, sh);
            s1 += __shfl_xor_sync(0xffffffffu, s1, sh);
            q1 += __shfl_xor_sync(0xffffffffu, q1, sh);
        }
        if (lane == 0) {
            redS[warp][2 * op] = s0; redQ[warp][2 * op] = q0;
            redS[warp][2 * op + 1] = s1; redQ[warp][2 * op + 1] = q1;
        }
    }
    __syncthreads();
    if (tid < 64) {
        int o = tid & 31;
        if (tid < 32) {
            float S = 0.f;
#pragma unroll
            for (int w = 0; w < 8; w++) S += redS[w][o];
            atomicAdd(&g_sum[o], S);
        } else {
            float Q = 0.f;
#pragma unroll
            for (int w = 0; w < 8; w++) Q += redQ[w][o];
            atomicAdd(&g_sq[o], Q);
        }
    }
}

// ---------------------------------------------------------------------------
// In-place BatchNorm (batch stats) + affine + ReLU.
__global__ void k_final(float* __restrict__ z, const float* __restrict__ gamma,
                        const float* __restrict__ beta) {
    int idx = blockIdx.x * 256 + threadIdx.x;   // float4 index, total 1769472
    int o = (idx / 27648) & 31;                 // 27648 float4 per (b,o) plane
    float mu = g_sum[o] * (1.f / (float)NBN);
    float var = g_sq[o] * (1.f / (float)NBN) - mu * mu;
    float inv = rsqrtf(var + 1e-5f);
    float sc = gamma[o] * inv;
    float sh = beta[o] - mu * sc;
    float4* p = (float4*)z;
    float4 v = p[idx];
    v.x = fmaxf(v.x * sc + sh, 0.f);
    v.y = fmaxf(v.y * sc + sh, 0.f);
    v.z = fmaxf(v.z * sc + sh, 0.f);
    v.w = fmaxf(v.w * sc + sh, 0.f);
    p[idx] = v;
}

// ---------------------------------------------------------------------------
extern "C" void kernel_launch(void* const* d_in, const int* in_sizes, int n_in,
                              void* d_out, int out_size) {
    const float* x       = (const float*)d_in[0];
    const float* w1_low  = (const float*)d_in[1];
    const float* w2_low  = (const float*)d_in[2];
    const float* w1_high = (const float*)d_in[3];
    const float* w2_high = (const float*)d_in[4];
    const float* w_fuse  = (const float*)d_in[5];
    const float* b_fuse  = (const float*)d_in[6];
    const float* gamma   = (const float*)d_in[7];
    const float* beta    = (const float*)d_in[8];
    float* out = (float*)d_out;

    k_parity<<<dim3(18, 64), 256>>>(x);
    k_attn<<<1, 256>>>(w1_low, w2_low, w1_high, w2_high, w_fuse);
    k_conv<<<dim3(216, 2), 256>>>(x, b_fuse, out);
    k_final<<<6912, 256>>>(out, gamma, beta);
}